// round 15
// baseline (speedup 1.0000x reference)
#include <cuda_runtime.h>
#include <cuda_fp16.h>
#include <cstdint>

// ===========================================================================
// Beam search tree: one fp16 GEMM (mma.sync fallback HMMA, sm_103-safe)
//   Y[B,256] = X[B,128] x W'[256,128]^T,  W' rows interleaved (re_j, im_j).
// Single-pass fp16 (R14 precision budget: rel_err ~6.1e-4, 39% gate margin).
// THIS ROUND: convert X to fp16 ONCE per tile (R7-style loader, hi only);
// GEMM loop uses 2 LDSM.x4 per warp per k-step for A (was 8 LDS.64 + 8 CVT,
// 4x-redundant across nwarp warps). Same MMA order -> bit-identical rel_err.
// 512 thr, 1 CTA/SM, 128-row tiles, 2 barriers/tile.
// ===========================================================================

#define GRID    152
#define NTILES  1024            // 131072 rows / 128
#define THREADS 512

#define OFF_XHI 0               // X fp16 [128][128] swizzled (32KB)
#define OFF_W   32768           // W fp16 [256][128] swizzled (64KB)
#define OFF_DIF 98304           // diffs [64][130] f32        (33280B)
#define DSTR    130
#define SMEM_TOTAL (98304 + 64 * DSTR * 4)   // 131584

typedef unsigned long long u64;

__device__ __host__ __forceinline__ int swz256(int a) { return a ^ ((a >> 4) & 0x70); }

__device__ __forceinline__ uint32_t smem_u32(const void* p) {
    uint32_t a;
    asm("{ .reg .u64 t; cvta.to.shared.u64 t, %1; cvt.u32.u64 %0, t; }" : "=r"(a) : "l"(p));
    return a;
}
#define LDSM4(r, a) \
    asm volatile("ldmatrix.sync.aligned.m8n8.x4.shared.b16 {%0,%1,%2,%3}, [%4];" \
        : "=r"((r)[0]), "=r"((r)[1]), "=r"((r)[2]), "=r"((r)[3]) : "r"(a))

__device__ __forceinline__ void mma_f16(float* d, const uint32_t* a, uint32_t b0, uint32_t b1) {
    asm volatile("mma.sync.aligned.m16n8k16.row.col.f32.f16.f16.f32 "
        "{%0,%1,%2,%3}, {%4,%5,%6,%7}, {%8,%9}, {%0,%1,%2,%3};"
        : "+f"(d[0]), "+f"(d[1]), "+f"(d[2]), "+f"(d[3])
        : "r"(a[0]), "r"(a[1]), "r"(a[2]), "r"(a[3]), "r"(b0), "r"(b1));
}

__device__ __forceinline__ float sigm_neg(float d) {   // 1/(1+exp(d))
    return 1.0f / (1.0f + __expf(d));
}
__device__ __forceinline__ uint32_t h2raw(__half2 h) { return *(uint32_t*)&h; }

// ---------------------------------------------------------------------------
// Prep: W' fp16 image in final smem layout (unchanged).
// Row n: n=2j -> re coeffs of beam j ([wr | -wi]); n=2j+1 -> im ([wi | wr]).
// ---------------------------------------------------------------------------
__device__ __align__(16) unsigned short g_W[32768];

__device__ __forceinline__ void store_w(int n, int k, float v) {
    __half h = __float2half(v);
    g_W[swz256(n * 256 + 2 * k) >> 1] = *(unsigned short*)&h;
}

__global__ void prep_kernel(const float* __restrict__ t0, const float* __restrict__ t1,
                            const float* __restrict__ t2, const float* __restrict__ t3,
                            const float* __restrict__ t4) {
    int idx = blockIdx.x * blockDim.x + threadIdx.x;
    if (idx >= 64 * 128) return;
    int a = idx >> 7;
    int j = idx & 127;
    float wr = 0.0f, wi = 0.0f;
    if (j < 62) {
        const float* th; int rel;
        if (j < 2)       { th = t0; rel = j; }
        else if (j < 6)  { th = t1; rel = j - 2; }
        else if (j < 14) { th = t2; rel = j - 6; }
        else if (j < 30) { th = t3; rel = j - 14; }
        else             { th = t4; rel = j - 30; }
        int node = rel >> 1, child = rel & 1;
        float theta = th[(node * 64 + a) * 2 + child];
        float s, c;
        sincosf(theta, &s, &c);
        wr = c * 0.125f;  wi = s * 0.125f;
    } else if (j < 126) {
        int jj = j - 62;
        double cmin = cos(3.14159265358979323846 - 1e-6);
        double cj   = 1.0 + (double)jj * ((cmin - 1.0) / 63.0);
        double ph   = 3.14159265358979323846 * (double)a * cj;
        double s, c;
        sincos(ph, &s, &c);
        wr = (float)(c * 0.125);  wi = (float)(s * 0.125);
    }
    store_w(2 * j,     a,      wr);
    store_w(2 * j,     64 + a, -wi);
    store_w(2 * j + 1, a,      wi);
    store_w(2 * j + 1, 64 + a, wr);
}

// ---------------------------------------------------------------------------
// Convert + STS: one thread's 8 float4 -> fp16 hi image (swizzled).
// ---------------------------------------------------------------------------
__device__ __forceinline__ void cvt_store_hi(char* smem, int tid, const float4* v) {
    #pragma unroll
    for (int i = 0; i < 8; i++) {
        int i4 = tid + THREADS * i;          // 0..4095
        int row = i4 >> 5, c = i4 & 31;
        int boff = swz256(row * 256 + c * 8);
        __half2 h0 = __float22half2_rn(make_float2(v[i].x, v[i].y));
        __half2 h1 = __float22half2_rn(make_float2(v[i].z, v[i].w));
        *(u64*)(smem + OFF_XHI + boff) = (u64)h2raw(h0) | ((u64)h2raw(h1) << 32);
    }
}

// ---------------------------------------------------------------------------
// Main persistent kernel: 16 warps = 4(M) x 4(N), warp tile 32 rows x 64 cols.
// ---------------------------------------------------------------------------
__global__ void __launch_bounds__(THREADS, 1)
beam_kernel(const float* __restrict__ x, float* __restrict__ out) {
    extern __shared__ char smem[];
    const uint32_t sb = smem_u32(smem);
    float* const dif = (float*)(smem + OFF_DIF);
    const int tid  = threadIdx.x;
    const int lane = tid & 31;
    const int wid  = tid >> 5;
    const int bid  = blockIdx.x;

    const int nwarp = wid >> 2, mwarp = wid & 3;   // SMSP-balanced layout
    const int m0 = mwarp * 32, n0 = nwarp * 64;
    const int lrow = lane & 15;
    const int kh2  = (lane >> 4) * 16;
    const int g    = lane >> 2, tig = lane & 3;

    uint32_t baseA[2], xmA[2], baseB[4], xmB[4];
    #pragma unroll
    for (int mb = 0; mb < 2; mb++) {
        int r = m0 + mb * 16 + lrow;
        baseA[mb] = sb + OFF_XHI + (r << 8);
        xmA[mb]   = (r & 7) << 4;
    }
    #pragma unroll
    for (int np = 0; np < 4; np++) {
        int r = n0 + np * 16 + lrow;
        baseB[np] = sb + OFF_W + (r << 8);
        xmB[np]   = (r & 7) << 4;
    }

    const int n_it = (NTILES - 1 - bid) / GRID + 1;

    // ---- Prologue: stage W (64KB) + load/convert tile 0 ----
    {
        float4*       d1 = (float4*)(smem + OFF_W);
        const float4* s1 = (const float4*)g_W;
        #pragma unroll
        for (int i = tid; i < 4096; i += THREADS) d1[i] = s1[i];
        const float4* gx = (const float4*)(x + (long)bid * 16384);
        float4 v[8];
        #pragma unroll
        for (int i = 0; i < 8; i++) v[i] = gx[tid + THREADS * i];
        cvt_store_hi(smem, tid, v);
    }
    __syncthreads();

    for (int it = 0; it < n_it; it++) {
        const long tile = bid + (long)it * GRID;

        // ========== phase B: GEMM(it) via LDSM, + pair diffs ==========
        float acc[2][8][4];
        #pragma unroll
        for (int mb = 0; mb < 2; mb++)
            #pragma unroll
            for (int nb = 0; nb < 8; nb++)
                #pragma unroll
                for (int c = 0; c < 4; c++) acc[mb][nb][c] = 0.0f;

        #pragma unroll
        for (int s = 0; s < 8; s++) {
            const int k2 = 32 * s + kh2;
            uint32_t ah[2][4], bh[4][4];
            #pragma unroll
            for (int mb = 0; mb < 2; mb++) LDSM4(ah[mb], baseA[mb] + (k2 ^ xmA[mb]));
            #pragma unroll
            for (int np = 0; np < 4; np++) LDSM4(bh[np], baseB[np] + (k2 ^ xmB[np]));
            // single pass: 16 independent MMAs (distance 16)
            #pragma unroll
            for (int mb = 0; mb < 2; mb++)
                #pragma unroll
                for (int np = 0; np < 4; np++) {
                    mma_f16(acc[mb][2*np],   ah[mb], bh[np][0], bh[np][2]);
                    mma_f16(acc[mb][2*np+1], ah[mb], bh[np][1], bh[np][3]);
                }
        }

        // ---- Pair diffs d_q = g(2q+1) - g(2q); partner via shfl.xor(1) ----
        #pragma unroll
        for (int mb = 0; mb < 2; mb++)
            #pragma unroll
            for (int nb = 0; nb < 8; nb++) {
                float g0 = acc[mb][nb][0] * acc[mb][nb][0] + acc[mb][nb][1] * acc[mb][nb][1];
                float g1 = acc[mb][nb][2] * acc[mb][nb][2] + acc[mb][nb][3] * acc[mb][nb][3];
                float og0 = __shfl_xor_sync(0xffffffffu, g0, 1);
                float og1 = __shfl_xor_sync(0xffffffffu, g1, 1);
                if ((tig & 1) == 0) {
                    int j = (n0 >> 1) + nb * 4 + tig;   // even beam of the pair
                    int q = j >> 1;                     // pair index 0..63
                    int m = m0 + mb * 16 + g;
                    dif[q * DSTR + m]     = og0 - g0;
                    dif[q * DSTR + m + 8] = og1 - g1;
                }
            }
        __syncthreads();

        // ========== phase A: LDG(it+1) -> epilogue(it) -> cvt+STS(it+1) ==========
        const bool hn = (it + 1) < n_it;
        float4 v[8];
        if (hn) {
            const float4* gx = (const float4*)(x + (tile + GRID) * 16384);
            #pragma unroll
            for (int i = 0; i < 8; i++) v[i] = gx[tid + THREADS * i];
        }
        {
            const int row = tid >> 2, s = tid & 3;
            float p0 = sigm_neg(dif[row]);                       // q=0
            float f  = ((s >> 1) == 0) ? p0 : 1.0f - p0;
            p0 = sigm_neg(dif[(1 + (s >> 1)) * DSTR + row]);     // q=1+(s>>1)
            f *= ((s & 1) == 0) ? p0 : 1.0f - p0;
            float rp2[2];
            p0 = sigm_neg(dif[(3 + s) * DSTR + row]);
            rp2[0] = f * p0;  rp2[1] = f - f * p0;
            float rp3[4];
            #pragma unroll
            for (int j = 0; j < 2; j++) {
                p0 = sigm_neg(dif[(7 + 2 * s + j) * DSTR + row]);
                rp3[2*j] = rp2[j] * p0;  rp3[2*j+1] = rp2[j] - rp2[j] * p0;
            }
            float rp4[8];
            #pragma unroll
            for (int j = 0; j < 4; j++) {
                p0 = sigm_neg(dif[(15 + 4 * s + j) * DSTR + row]);
                rp4[2*j] = rp3[j] * p0;  rp4[2*j+1] = rp3[j] - rp3[j] * p0;
            }
            float rp5[16];
            #pragma unroll
            for (int j = 0; j < 8; j++) {
                p0 = sigm_neg(dif[(31 + 8 * s + j) * DSTR + row]);
                rp5[2*j] = rp4[j] * p0;  rp5[2*j+1] = rp4[j] - rp4[j] * p0;
            }
            float4* o4 = (float4*)(out + (tile * 128 + row) * 64 + 16 * s);
            #pragma unroll
            for (int j = 0; j < 4; j++)
                o4[j] = make_float4(rp5[4*j], rp5[4*j+1], rp5[4*j+2], rp5[4*j+3]);
        }
        if (hn) cvt_store_hi(smem, tid, v);
        __syncthreads();
    }
}

// ---------------------------------------------------------------------------
extern "C" void kernel_launch(void* const* d_in, const int* in_sizes, int n_in,
                              void* d_out, int out_size) {
    const float* x  = (const float*)d_in[0];
    const float* t0 = (const float*)d_in[1];
    const float* t1 = (const float*)d_in[2];
    const float* t2 = (const float*)d_in[3];
    const float* t3 = (const float*)d_in[4];
    const float* t4 = (const float*)d_in[5];
    float* out = (float*)d_out;

    prep_kernel<<<32, 256>>>(t0, t1, t2, t3, t4);

    cudaFuncSetAttribute(beam_kernel, cudaFuncAttributeMaxDynamicSharedMemorySize, SMEM_TOTAL);
    beam_kernel<<<GRID, THREADS, SMEM_TOTAL>>>(x, out);
}

// round 16
// speedup vs baseline: 1.5932x; 1.5932x over previous
#include <cuda_runtime.h>
#include <cuda_fp16.h>
#include <cstdint>

// ===========================================================================
// Beam search tree: one fp16 GEMM (mma.sync fallback HMMA, sm_103-safe)
//   Y[B,256] = X[B,128] x W'[256,128]^T,  W' rows interleaved (re_j, im_j).
// Single-pass fp16 (rel_err ~6.1e-4, 39% gate margin, R14-calibrated).
// THIS ROUND: cp.async fp32 -> linear smem staging (R14 loader, zero reg
// cost) + dedicated smem->smem convert phase -> swizzled fp16 image +
// pure-LDSM GEMM (R15 phase B). Per tile:
//   [GEMM+diffs | cp.async(t+1) + epilogue(t) + wait | convert -> image]
// 512 thr, 1 CTA/SM, 128-row tiles, 3 barriers/tile.
// ===========================================================================

#define GRID    152
#define NTILES  1024            // 131072 rows / 128
#define THREADS 512

#define OFF_XF32 0              // X fp32 staging [128][128] linear (64KB)
#define OFF_XHI  65536          // X fp16 image [128][128] swizzled (32KB)
#define OFF_W    98304          // W fp16 [256][128] swizzled       (64KB)
#define OFF_DIF  163840         // diffs [64][130] f32              (33280B)
#define DSTR     130
#define SMEM_TOTAL (163840 + 64 * DSTR * 4)   // 197120

typedef unsigned long long u64;

__device__ __host__ __forceinline__ int swz256(int a) { return a ^ ((a >> 4) & 0x70); }

__device__ __forceinline__ uint32_t smem_u32(const void* p) {
    uint32_t a;
    asm("{ .reg .u64 t; cvta.to.shared.u64 t, %1; cvt.u32.u64 %0, t; }" : "=r"(a) : "l"(p));
    return a;
}
#define LDSM4(r, a) \
    asm volatile("ldmatrix.sync.aligned.m8n8.x4.shared.b16 {%0,%1,%2,%3}, [%4];" \
        : "=r"((r)[0]), "=r"((r)[1]), "=r"((r)[2]), "=r"((r)[3]) : "r"(a))

__device__ __forceinline__ void mma_f16(float* d, const uint32_t* a, uint32_t b0, uint32_t b1) {
    asm volatile("mma.sync.aligned.m16n8k16.row.col.f32.f16.f16.f32 "
        "{%0,%1,%2,%3}, {%4,%5,%6,%7}, {%8,%9}, {%0,%1,%2,%3};"
        : "+f"(d[0]), "+f"(d[1]), "+f"(d[2]), "+f"(d[3])
        : "r"(a[0]), "r"(a[1]), "r"(a[2]), "r"(a[3]), "r"(b0), "r"(b1));
}

__device__ __forceinline__ float sigm_neg(float d) {   // 1/(1+exp(d))
    return 1.0f / (1.0f + __expf(d));
}
__device__ __forceinline__ uint32_t h2raw(__half2 h) { return *(uint32_t*)&h; }

// ---------------------------------------------------------------------------
// Prep: W' fp16 image in final smem layout (unchanged).
// Row n: n=2j -> re coeffs of beam j ([wr | -wi]); n=2j+1 -> im ([wi | wr]).
// ---------------------------------------------------------------------------
__device__ __align__(16) unsigned short g_W[32768];

__device__ __forceinline__ void store_w(int n, int k, float v) {
    __half h = __float2half(v);
    g_W[swz256(n * 256 + 2 * k) >> 1] = *(unsigned short*)&h;
}

__global__ void prep_kernel(const float* __restrict__ t0, const float* __restrict__ t1,
                            const float* __restrict__ t2, const float* __restrict__ t3,
                            const float* __restrict__ t4) {
    int idx = blockIdx.x * blockDim.x + threadIdx.x;
    if (idx >= 64 * 128) return;
    int a = idx >> 7;
    int j = idx & 127;
    float wr = 0.0f, wi = 0.0f;
    if (j < 62) {
        const float* th; int rel;
        if (j < 2)       { th = t0; rel = j; }
        else if (j < 6)  { th = t1; rel = j - 2; }
        else if (j < 14) { th = t2; rel = j - 6; }
        else if (j < 30) { th = t3; rel = j - 14; }
        else             { th = t4; rel = j - 30; }
        int node = rel >> 1, child = rel & 1;
        float theta = th[(node * 64 + a) * 2 + child];
        float s, c;
        sincosf(theta, &s, &c);
        wr = c * 0.125f;  wi = s * 0.125f;
    } else if (j < 126) {
        int jj = j - 62;
        double cmin = cos(3.14159265358979323846 - 1e-6);
        double cj   = 1.0 + (double)jj * ((cmin - 1.0) / 63.0);
        double ph   = 3.14159265358979323846 * (double)a * cj;
        double s, c;
        sincos(ph, &s, &c);
        wr = (float)(c * 0.125);  wi = (float)(s * 0.125);
    }
    store_w(2 * j,     a,      wr);
    store_w(2 * j,     64 + a, -wi);
    store_w(2 * j + 1, a,      wi);
    store_w(2 * j + 1, 64 + a, wr);
}

// ---------------------------------------------------------------------------
// cp.async: 128x128 fp32 tile -> linear smem staging. 8 x 16B per thread.
// ---------------------------------------------------------------------------
__device__ __forceinline__ void issue_x_async(uint32_t sb, const float* __restrict__ gx, int tid) {
    #pragma unroll
    for (int i = 0; i < 8; i++) {
        int i4 = tid + THREADS * i;          // 16B-chunk id 0..4095
        uint32_t sa = sb + OFF_XF32 + i4 * 16;
        asm volatile("cp.async.ca.shared.global [%0], [%1], 16;"
                     :: "r"(sa), "l"(gx + i4 * 4) : "memory");
    }
    asm volatile("cp.async.commit_group;" ::: "memory");
}

// ---------------------------------------------------------------------------
// Convert phase: fp32 staging -> swizzled fp16 image (smem to smem).
// ---------------------------------------------------------------------------
__device__ __forceinline__ void convert_image(char* smem, int tid) {
    #pragma unroll
    for (int i = 0; i < 8; i++) {
        int i4 = tid + THREADS * i;          // 0..4095
        float4 v = *(const float4*)(smem + OFF_XF32 + i4 * 16);
        int row = i4 >> 5, c = i4 & 31;
        int boff = swz256(row * 256 + c * 8);
        __half2 h0 = __float22half2_rn(make_float2(v.x, v.y));
        __half2 h1 = __float22half2_rn(make_float2(v.z, v.w));
        *(u64*)(smem + OFF_XHI + boff) = (u64)h2raw(h0) | ((u64)h2raw(h1) << 32);
    }
}

// ---------------------------------------------------------------------------
// Main persistent kernel: 16 warps = 4(M) x 4(N), warp tile 32 rows x 64 cols.
// ---------------------------------------------------------------------------
__global__ void __launch_bounds__(THREADS, 1)
beam_kernel(const float* __restrict__ x, float* __restrict__ out) {
    extern __shared__ char smem[];
    const uint32_t sb = smem_u32(smem);
    float* const dif = (float*)(smem + OFF_DIF);
    const int tid  = threadIdx.x;
    const int lane = tid & 31;
    const int wid  = tid >> 5;
    const int bid  = blockIdx.x;

    const int nwarp = wid >> 2, mwarp = wid & 3;   // SMSP-balanced layout
    const int m0 = mwarp * 32, n0 = nwarp * 64;
    const int lrow = lane & 15;
    const int kh2  = (lane >> 4) * 16;
    const int g    = lane >> 2, tig = lane & 3;

    uint32_t baseA[2], xmA[2], baseB[4], xmB[4];
    #pragma unroll
    for (int mb = 0; mb < 2; mb++) {
        int r = m0 + mb * 16 + lrow;
        baseA[mb] = sb + OFF_XHI + (r << 8);
        xmA[mb]   = (r & 7) << 4;
    }
    #pragma unroll
    for (int np = 0; np < 4; np++) {
        int r = n0 + np * 16 + lrow;
        baseB[np] = sb + OFF_W + (r << 8);
        xmB[np]   = (r & 7) << 4;
    }

    const int n_it = (NTILES - 1 - bid) / GRID + 1;

    // ---- Prologue: cp.async tile 0 + stage W, then build image 0 ----
    issue_x_async(sb, x + (long)bid * 16384, tid);
    {
        float4*       d1 = (float4*)(smem + OFF_W);
        const float4* s1 = (const float4*)g_W;
        #pragma unroll
        for (int i = tid; i < 4096; i += THREADS) d1[i] = s1[i];
    }
    asm volatile("cp.async.wait_group 0;" ::: "memory");
    __syncthreads();
    convert_image(smem, tid);
    __syncthreads();

    for (int it = 0; it < n_it; it++) {
        const long tile = bid + (long)it * GRID;

        // ========== phase B: GEMM(it) via LDSM, + pair diffs ==========
        float acc[2][8][4];
        #pragma unroll
        for (int mb = 0; mb < 2; mb++)
            #pragma unroll
            for (int nb = 0; nb < 8; nb++)
                #pragma unroll
                for (int c = 0; c < 4; c++) acc[mb][nb][c] = 0.0f;

        #pragma unroll
        for (int s = 0; s < 8; s++) {
            const int k2 = 32 * s + kh2;
            uint32_t ah[2][4], bh[4][4];
            #pragma unroll
            for (int mb = 0; mb < 2; mb++) LDSM4(ah[mb], baseA[mb] + (k2 ^ xmA[mb]));
            #pragma unroll
            for (int np = 0; np < 4; np++) LDSM4(bh[np], baseB[np] + (k2 ^ xmB[np]));
            // single pass: 16 independent MMAs (distance 16)
            #pragma unroll
            for (int mb = 0; mb < 2; mb++)
                #pragma unroll
                for (int np = 0; np < 4; np++) {
                    mma_f16(acc[mb][2*np],   ah[mb], bh[np][0], bh[np][2]);
                    mma_f16(acc[mb][2*np+1], ah[mb], bh[np][1], bh[np][3]);
                }
        }

        // ---- Pair diffs d_q = g(2q+1) - g(2q); partner via shfl.xor(1) ----
        #pragma unroll
        for (int mb = 0; mb < 2; mb++)
            #pragma unroll
            for (int nb = 0; nb < 8; nb++) {
                float g0 = acc[mb][nb][0] * acc[mb][nb][0] + acc[mb][nb][1] * acc[mb][nb][1];
                float g1 = acc[mb][nb][2] * acc[mb][nb][2] + acc[mb][nb][3] * acc[mb][nb][3];
                float og0 = __shfl_xor_sync(0xffffffffu, g0, 1);
                float og1 = __shfl_xor_sync(0xffffffffu, g1, 1);
                if ((tig & 1) == 0) {
                    int j = (n0 >> 1) + nb * 4 + tig;   // even beam of the pair
                    int q = j >> 1;                     // pair index 0..63
                    int m = m0 + mb * 16 + g;
                    dif[q * DSTR + m]     = og0 - g0;
                    dif[q * DSTR + m + 8] = og1 - g1;
                }
            }
        __syncthreads();

        // ========== phase A: cp.async(it+1) + epilogue(it) ==========
        const bool hn = (it + 1) < n_it;
        if (hn) issue_x_async(sb, x + (tile + GRID) * 16384, tid);
        {
            const int row = tid >> 2, s = tid & 3;
            float p0 = sigm_neg(dif[row]);                       // q=0
            float f  = ((s >> 1) == 0) ? p0 : 1.0f - p0;
            p0 = sigm_neg(dif[(1 + (s >> 1)) * DSTR + row]);     // q=1+(s>>1)
            f *= ((s & 1) == 0) ? p0 : 1.0f - p0;
            float rp2[2];
            p0 = sigm_neg(dif[(3 + s) * DSTR + row]);
            rp2[0] = f * p0;  rp2[1] = f - f * p0;
            float rp3[4];
            #pragma unroll
            for (int j = 0; j < 2; j++) {
                p0 = sigm_neg(dif[(7 + 2 * s + j) * DSTR + row]);
                rp3[2*j] = rp2[j] * p0;  rp3[2*j+1] = rp2[j] - rp2[j] * p0;
            }
            float rp4[8];
            #pragma unroll
            for (int j = 0; j < 4; j++) {
                p0 = sigm_neg(dif[(15 + 4 * s + j) * DSTR + row]);
                rp4[2*j] = rp3[j] * p0;  rp4[2*j+1] = rp3[j] - rp3[j] * p0;
            }
            float rp5[16];
            #pragma unroll
            for (int j = 0; j < 8; j++) {
                p0 = sigm_neg(dif[(31 + 8 * s + j) * DSTR + row]);
                rp5[2*j] = rp4[j] * p0;  rp5[2*j+1] = rp4[j] - rp4[j] * p0;
            }
            float4* o4 = (float4*)(out + (tile * 128 + row) * 64 + 16 * s);
            #pragma unroll
            for (int j = 0; j < 4; j++)
                o4[j] = make_float4(rp5[4*j], rp5[4*j+1], rp5[4*j+2], rp5[4*j+3]);
        }
        if (hn) {
            asm volatile("cp.async.wait_group 0;" ::: "memory");
            __syncthreads();
            // ========== phase C: build fp16 image of tile it+1 ==========
            convert_image(smem, tid);
        }
        __syncthreads();
    }
}

// ---------------------------------------------------------------------------
extern "C" void kernel_launch(void* const* d_in, const int* in_sizes, int n_in,
                              void* d_out, int out_size) {
    const float* x  = (const float*)d_in[0];
    const float* t0 = (const float*)d_in[1];
    const float* t1 = (const float*)d_in[2];
    const float* t2 = (const float*)d_in[3];
    const float* t3 = (const float*)d_in[4];
    const float* t4 = (const float*)d_in[5];
    float* out = (float*)d_out;

    prep_kernel<<<32, 256>>>(t0, t1, t2, t3, t4);

    cudaFuncSetAttribute(beam_kernel, cudaFuncAttributeMaxDynamicSharedMemorySize, SMEM_TOTAL);
    beam_kernel<<<GRID, THREADS, SMEM_TOTAL>>>(x, out);
}